// round 4
// baseline (speedup 1.0000x reference)
#include <cuda_runtime.h>
#include <cstdint>

#define ROWS            128
#define ROW_N           262144          // 256*32*32
#define BLOCKS_PER_ROW  64
#define SEG_N           (ROW_N / BLOCKS_PER_ROW)   // 4096 elements per block
#define THREADS         256
#define VEC_PER_THREAD  (SEG_N / 4 / THREADS)      // 4 float4 per thread
#define TOPK            5
#define CAND_PER_ROW    (BLOCKS_PER_ROW * TOPK)    // 320

// Scratch: per-(row,segment) top-5 candidates. __device__ globals (no cudaMalloc allowed).
__device__ float g_cand_val[ROWS * BLOCKS_PER_ROW * TOPK];
__device__ int   g_cand_idx[ROWS * BLOCKS_PER_ROW * TOPK];

// Ordering matching jax.lax.top_k stability: larger value wins; equal value -> smaller index wins.
__device__ __forceinline__ bool better(float v, int i, float bv, int bi) {
    return (v > bv) || (v == bv && i < bi);
}

// Insert (val, idx) into a sorted-descending 5-entry register list.
__device__ __forceinline__ void ins5(float val, int idx, float v[TOPK], int id[TOPK]) {
    if (!better(val, idx, v[TOPK - 1], id[TOPK - 1])) return;   // common fast path
    v[TOPK - 1] = val; id[TOPK - 1] = idx;
    #pragma unroll
    for (int j = TOPK - 1; j > 0; --j) {
        if (better(v[j], id[j], v[j - 1], id[j - 1])) {
            float tv = v[j]; v[j] = v[j - 1]; v[j - 1] = tv;
            int   ti = id[j]; id[j] = id[j - 1]; id[j - 1] = ti;
        } else break;
    }
}

// ---------------------------------------------------------------------------
// Stage 1: fused  (read x) + (zero out) + (per-segment top-5 -> scratch)
// grid = ROWS * BLOCKS_PER_ROW, block = 256
// ---------------------------------------------------------------------------
__global__ __launch_bounds__(THREADS)
void wta_stage1(const float* __restrict__ x, float* __restrict__ out) {
    const int b   = blockIdx.x;
    const int row = b >> 6;          // / BLOCKS_PER_ROW
    const int seg = b & 63;          // % BLOCKS_PER_ROW
    const int t   = threadIdx.x;

    const size_t base = (size_t)row * ROW_N + (size_t)seg * SEG_N;
    const float4* __restrict__ xv = (const float4*)(x + base);
    float4* __restrict__       ov = (float4*)(out + base);

    float v[TOPK]; int id[TOPK];
    #pragma unroll
    for (int j = 0; j < TOPK; ++j) { v[j] = -INFINITY; id[j] = 0x7fffffff; }

    // Batched streaming loads (MLP=4), streaming zero-stores, local top-5.
    float4 d[VEC_PER_THREAD];
    #pragma unroll
    for (int k = 0; k < VEC_PER_THREAD; ++k)
        d[k] = __ldcs(&xv[k * THREADS + t]);

    const float4 z = make_float4(0.f, 0.f, 0.f, 0.f);
    #pragma unroll
    for (int k = 0; k < VEC_PER_THREAD; ++k)
        __stcs(&ov[k * THREADS + t], z);

    #pragma unroll
    for (int k = 0; k < VEC_PER_THREAD; ++k) {
        const int gi = seg * SEG_N + (k * THREADS + t) * 4;   // row-relative index
        ins5(d[k].x, gi + 0, v, id);
        ins5(d[k].y, gi + 1, v, id);
        ins5(d[k].z, gi + 2, v, id);
        ins5(d[k].w, gi + 3, v, id);
    }

    // Block reduction: 256 threads x 5 candidates = 1280 entries -> top-5.
    __shared__ float sval[THREADS * TOPK];
    __shared__ int   sidx[THREADS * TOPK];
    __shared__ float rv[THREADS];
    __shared__ int   ri[THREADS];
    __shared__ int   rp[THREADS];
    __shared__ float win_v[TOPK];
    __shared__ int   win_i[TOPK];

    #pragma unroll
    for (int j = 0; j < TOPK; ++j) {      // stride-5 writes: 5 coprime w/ 32 banks
        sval[t * TOPK + j] = v[j];
        sidx[t * TOPK + j] = id[j];
    }
    __syncthreads();

    for (int r = 0; r < TOPK; ++r) {
        float bv = -INFINITY; int bi = 0x7fffffff; int bp = -1;
        #pragma unroll
        for (int j = 0; j < TOPK; ++j) {
            const int e = t + j * THREADS;
            if (better(sval[e], sidx[e], bv, bi)) { bv = sval[e]; bi = sidx[e]; bp = e; }
        }
        rv[t] = bv; ri[t] = bi; rp[t] = bp;
        __syncthreads();
        #pragma unroll
        for (int s = THREADS / 2; s > 0; s >>= 1) {
            if (t < s && better(rv[t + s], ri[t + s], rv[t], ri[t])) {
                rv[t] = rv[t + s]; ri[t] = ri[t + s]; rp[t] = rp[t + s];
            }
            __syncthreads();
        }
        if (t == 0) {
            win_v[r] = rv[0]; win_i[r] = ri[0];
            sval[rp[0]] = -INFINITY;           // exclude winner
        }
        __syncthreads();
    }

    if (t < TOPK) {
        const int o = (row * BLOCKS_PER_ROW + seg) * TOPK + t;
        g_cand_val[o] = win_v[t];
        g_cand_idx[o] = win_i[t];
    }
}

// ---------------------------------------------------------------------------
// Stage 2: per-row reduce 320 candidates -> exact top-5; scatter 1.0f.
// grid = ROWS, block = 256
// ---------------------------------------------------------------------------
__global__ __launch_bounds__(THREADS)
void wta_stage2(float* __restrict__ out) {
    const int row = blockIdx.x;
    const int t   = threadIdx.x;

    __shared__ float sval[CAND_PER_ROW];
    __shared__ int   sidx[CAND_PER_ROW];
    __shared__ float rv[THREADS];
    __shared__ int   ri[THREADS];
    __shared__ int   rp[THREADS];
    __shared__ int   win[TOPK];

    for (int e = t; e < CAND_PER_ROW; e += THREADS) {
        sval[e] = g_cand_val[row * CAND_PER_ROW + e];
        sidx[e] = g_cand_idx[row * CAND_PER_ROW + e];
    }
    __syncthreads();

    for (int r = 0; r < TOPK; ++r) {
        float bv = -INFINITY; int bi = 0x7fffffff; int bp = -1;
        for (int e = t; e < CAND_PER_ROW; e += THREADS) {
            if (better(sval[e], sidx[e], bv, bi)) { bv = sval[e]; bi = sidx[e]; bp = e; }
        }
        rv[t] = bv; ri[t] = bi; rp[t] = bp;
        __syncthreads();
        #pragma unroll
        for (int s = THREADS / 2; s > 0; s >>= 1) {
            if (t < s && better(rv[t + s], ri[t + s], rv[t], ri[t])) {
                rv[t] = rv[t + s]; ri[t] = ri[t + s]; rp[t] = rp[t + s];
            }
            __syncthreads();
        }
        if (t == 0) {
            win[r] = ri[0];
            sval[rp[0]] = -INFINITY;
        }
        __syncthreads();
    }

    if (t < TOPK)
        out[(size_t)row * ROW_N + win[t]] = 1.0f;
}

// ---------------------------------------------------------------------------
extern "C" void kernel_launch(void* const* d_in, const int* in_sizes, int n_in,
                              void* d_out, int out_size) {
    const float* x = (const float*)d_in[0];
    float* out = (float*)d_out;
    // topk input (d_in[1]) is the compile-time constant 5 per the problem setup.
    wta_stage1<<<ROWS * BLOCKS_PER_ROW, THREADS>>>(x, out);
    wta_stage2<<<ROWS, THREADS>>>(out);
}